// round 17
// baseline (speedup 1.0000x reference)
#include <cuda_runtime.h>

// N=8192 rows, C=5000 classes, RATIO=3
#define NC    5000
#define NT    256
#define NW    8
#define NV4   1250          // float4 per row
#define CAPL  512           // per-row list / candidate capacity
#define NBF   512           // fine bins per row
#define PIVF  1.5f
#define PB    0x3FC00000u   // bits of 1.5f

__device__ double   g_loss = 0.0;
__device__ double   g_tsum = 0.0;
__device__ unsigned g_done = 0;

__device__ __forceinline__ unsigned fkey(float f) {        // fallback only
    unsigned b = __float_as_uint(f);
    return (b & 0x80000000u) ? ~b : (b | 0x80000000u);
}
__device__ __forceinline__ float kinv(unsigned k) {
    return __uint_as_float((k & 0x80000000u) ? (k & 0x7FFFFFFFu) : ~k);
}
__device__ __forceinline__ float sp(float x) {
    float l = __logf(1.f + __expf(-fabsf(x)));
    return x > 0.f ? x + l : l;
}
__device__ __forceinline__ unsigned fbin(unsigned b) {     // raw positive-float bits
    unsigned v = (b - PB) >> 19;
    return v > (NBF - 1) ? (NBF - 1) : v;
}

__global__ void __launch_bounds__(NT, 6)
hardneg(const float* __restrict__ pred, const float* __restrict__ target,
        float* __restrict__ out, int rows)
{
    __shared__ unsigned s_hist[2048];   // fast: A=[0,512) B=[512,1024) C=[1024,1536); fallback: all
    __shared__ unsigned s_lista[CAPL];
    __shared__ unsigned s_listb[CAPL];
    __shared__ unsigned s_listc[CAPL];
    __shared__ unsigned s_cand[CAPL];
    __shared__ unsigned s_wsum[NW];
    __shared__ unsigned s_pr1[NW];      // packed posA | posB<<16
    __shared__ unsigned s_pr2[NW];      // posC
    __shared__ float    s_accr[NW];
    __shared__ unsigned s_binv, s_kkv, s_tkey, s_krem;
    __shared__ int      s_cnta, s_cntb, s_cntc, s_ccnt;

    const int tid  = threadIdx.x;
    const int lane = tid & 31;
    const int wid  = tid >> 5;
    const int rowA = 3 * blockIdx.x;
    const bool hasB = (rowA + 1 < rows);
    const bool hasC = (rowA + 2 < rows);

    const float*  prowA = pred   + (size_t)rowA * NC;
    const float*  trowA = target + (size_t)rowA * NC;
    const float*  prowB = hasB ? (prowA + NC) : prowA;
    const float*  trowB = hasB ? (trowA + NC) : trowA;
    const float*  prowC = hasC ? (prowA + 2 * NC) : prowA;
    const float*  trowC = hasC ? (trowA + 2 * NC) : trowA;
    const float4* pa4 = (const float4*)prowA;
    const float4* ta4 = (const float4*)trowA;
    const float4* pb4 = (const float4*)prowB;
    const float4* tb4 = (const float4*)trowB;
    const float4* pc4 = (const float4*)prowC;
    const float4* tc4 = (const float4*)trowC;

    ((uint4*)s_hist)[tid]       = make_uint4(0, 0, 0, 0);  // words [0,1024)
    if (tid < 128) ((uint4*)s_hist)[256 + tid] = make_uint4(0, 0, 0, 0);  // [1024,1536)
    if (tid == 0) { s_cnta = 0; s_cntb = 0; s_cntc = 0; s_ccnt = 0; }
    __syncthreads();

    // ======== hot pass: interleaved three-row stream (6 LDG.128 in flight) ========
    int   posA = 0, posB = 0, posC = 0;
    float acc  = 0.f;

    #define PROCX(px, tx, pcnt, cntp, listp)                                \
        do {                                                                \
            float _x = (px);                                                \
            if ((tx) != 0.f) {                                              \
                pcnt++; acc += sp(-_x);                                     \
            } else if (_x > PIVF) {                                         \
                int _s = atomicAdd(cntp, 1);                                \
                if (_s < CAPL) (listp)[_s] = __float_as_uint(_x);           \
            }                                                               \
        } while (0)

    #pragma unroll
    for (int j = 0; j < 5; j++) {
        int i = j * NT + tid;
        if (j < 4 || i < NV4) {
            float4 pa = __ldcs(&pa4[i]);
            float4 ta = __ldcs(&ta4[i]);
            float4 pb = __ldcs(&pb4[i]);
            float4 tb = __ldcs(&tb4[i]);
            float4 pc = __ldcs(&pc4[i]);
            float4 tc = __ldcs(&tc4[i]);
            PROCX(pa.x, ta.x, posA, &s_cnta, s_lista);
            PROCX(pa.y, ta.y, posA, &s_cnta, s_lista);
            PROCX(pa.z, ta.z, posA, &s_cnta, s_lista);
            PROCX(pa.w, ta.w, posA, &s_cnta, s_lista);
            if (hasB) {
                PROCX(pb.x, tb.x, posB, &s_cntb, s_listb);
                PROCX(pb.y, tb.y, posB, &s_cntb, s_listb);
                PROCX(pb.z, tb.z, posB, &s_cntb, s_listb);
                PROCX(pb.w, tb.w, posB, &s_cntb, s_listb);
            }
            if (hasC) {
                PROCX(pc.x, tc.x, posC, &s_cntc, s_listc);
                PROCX(pc.y, tc.y, posC, &s_cntc, s_listc);
                PROCX(pc.z, tc.z, posC, &s_cntc, s_listc);
                PROCX(pc.w, tc.w, posC, &s_cntc, s_listc);
            }
        }
    }
    #undef PROCX

    unsigned pk1 = (unsigned)posA | ((unsigned)posB << 16);
    unsigned pk2 = (unsigned)posC;
    #pragma unroll
    for (int off = 16; off; off >>= 1) {
        pk1 += __shfl_down_sync(0xFFFFFFFFu, pk1, off);
        pk2 += __shfl_down_sync(0xFFFFFFFFu, pk2, off);
    }
    if (lane == 0) { s_pr1[wid] = pk1; s_pr2[wid] = pk2; }
    __syncthreads();

    unsigned t1 = 0, t2 = 0;
    #pragma unroll
    for (int w = 0; w < NW; w++) { t1 += s_pr1[w]; t2 += s_pr2[w]; }
    const int postA = (int)(t1 & 0xFFFFu);
    const int postB = (int)(t1 >> 16);
    const int postC = (int)t2;

    // ================== per-row selection ==================
    #define SELECT_ROW(post, cntv, listv, HOFF, prow, trow)                      \
    {                                                                            \
        int k0 = 3 * (post);                                                     \
        if (k0 > NC - (post)) k0 = NC - (post);                                  \
        const unsigned kk = (unsigned)k0;                                        \
        const int  cnt  = (cntv);                                                \
        const bool fast = (cnt >= k0) && (cnt <= CAPL);                          \
        if (k0 > 0 && fast) {                                                    \
            for (int i = tid; i < cnt; i += NT)                                  \
                atomicAdd(&s_hist[(HOFF) + fbin((listv)[i])], 1u);               \
            __syncthreads();                                                     \
            unsigned w2[2];                                                      \
            unsigned S = 0;                                                      \
            w2[0] = s_hist[(HOFF) + tid * 2];                                    \
            w2[1] = s_hist[(HOFF) + tid * 2 + 1];                                \
            S = w2[0] + w2[1];                                                   \
            unsigned v = S;                                                      \
            _Pragma("unroll")                                                    \
            for (int off = 1; off < 32; off <<= 1) {                             \
                unsigned o = __shfl_down_sync(0xFFFFFFFFu, v, off);              \
                if (lane + off < 32) v += o;                                     \
            }                                                                    \
            if (lane == 0) s_wsum[wid] = v;                                      \
            __syncthreads();                                                     \
            unsigned above = v - S;                                              \
            _Pragma("unroll")                                                    \
            for (int w = wid + 1; w < NW; w++) above += s_wsum[w];               \
            if (above < kk && kk <= above + S) {                                 \
                unsigned a = above;                                              \
                if (kk <= a + w2[1]) { s_binv = (unsigned)(tid*2+1); s_kkv = kk - a; } \
                else { a += w2[1]; s_binv = (unsigned)(tid*2); s_kkv = kk - a; } \
            }                                                                    \
            __syncthreads();                                                     \
            const unsigned bv = s_binv;                                          \
            for (int i = tid; i < cnt; i += NT) {                                \
                unsigned key = (listv)[i];                                       \
                unsigned b   = fbin(key);                                        \
                if (b > bv) acc += sp(__uint_as_float(key));                     \
                else if (b == bv) {                                              \
                    int s = atomicAdd(&s_ccnt, 1);                               \
                    if (s < CAPL) s_cand[s] = key;                               \
                }                                                                \
            }                                                                    \
        } else if (k0 > 0) {                                                     \
            /* exact fallback: packed 4096-bin fkey histogram, global reread */  \
            ((uint4*)s_hist)[tid]      = make_uint4(0, 0, 0, 0);                 \
            ((uint4*)s_hist)[tid + NT] = make_uint4(0, 0, 0, 0);                 \
            __syncthreads();                                                     \
            for (int i = tid; i < NC; i += NT) {                                 \
                if ((trow)[i] == 0.f) {                                          \
                    unsigned k = fkey((prow)[i]);                                \
                    atomicAdd(&s_hist[k >> 21], ((k >> 20) & 1u) ? 65536u : 1u); \
                }                                                                \
            }                                                                    \
            __syncthreads();                                                     \
            unsigned w8[8];                                                      \
            unsigned S = 0;                                                      \
            _Pragma("unroll")                                                    \
            for (int j = 0; j < 8; j++) {                                        \
                unsigned vv = s_hist[tid * 8 + j];                               \
                w8[j] = vv;                                                      \
                S += (vv & 0xFFFFu) + (vv >> 16);                                \
            }                                                                    \
            unsigned v = S;                                                      \
            _Pragma("unroll")                                                    \
            for (int off = 1; off < 32; off <<= 1) {                             \
                unsigned o = __shfl_down_sync(0xFFFFFFFFu, v, off);              \
                if (lane + off < 32) v += o;                                     \
            }                                                                    \
            if (lane == 0) s_wsum[wid] = v;                                      \
            __syncthreads();                                                     \
            unsigned above = v - S;                                              \
            _Pragma("unroll")                                                    \
            for (int w = wid + 1; w < NW; w++) above += s_wsum[w];               \
            if (above < kk && kk <= above + S) {                                 \
                unsigned a = above;                                              \
                _Pragma("unroll")                                                \
                for (int j = 15; j >= 0; j--) {                                  \
                    unsigned wv = w8[j >> 1];                                    \
                    unsigned c  = (j & 1) ? (wv >> 16) : (wv & 0xFFFFu);         \
                    if (kk <= a + c) { s_binv = (unsigned)(tid*16+j); s_kkv = kk - a; break; } \
                    a += c;                                                      \
                }                                                                \
            }                                                                    \
            __syncthreads();                                                     \
            const unsigned bv = s_binv;                                          \
            for (int i = tid; i < NC; i += NT) {                                 \
                if ((trow)[i] == 0.f) {                                          \
                    unsigned k = fkey((prow)[i]);                                \
                    unsigned b = k >> 20;                                        \
                    if (b > bv) acc += sp(kinv(k));                              \
                    else if (b == bv) {                                          \
                        int s = atomicAdd(&s_ccnt, 1);                           \
                        if (s < CAPL) s_cand[s] = k;                             \
                    }                                                            \
                }                                                                \
            }                                                                    \
        }                                                                        \
        __syncthreads();                                                         \
        if (k0 > 0) {                                                            \
            int M = s_ccnt; if (M > CAPL) M = CAPL;                              \
            const unsigned kk2 = s_kkv;                                          \
            for (int c = tid; c < M; c += NT) {                                  \
                unsigned key = s_cand[c];                                        \
                unsigned gt = 0, eq = 0;                                         \
                for (int j = 0; j < M; j++) {                                    \
                    unsigned o = s_cand[j];                                      \
                    gt += (o > key);                                             \
                    eq += (o == key);                                            \
                }                                                                \
                if (gt < kk2 && kk2 <= gt + eq) { s_tkey = key; s_krem = kk2 - gt; } \
            }                                                                    \
        }                                                                        \
        __syncthreads();                                                         \
        if (k0 > 0) {                                                            \
            const unsigned tk = s_tkey;                                          \
            int M = s_ccnt; if (M > CAPL) M = CAPL;                              \
            for (int c = tid; c < M; c += NT) {                                  \
                unsigned key = s_cand[c];                                        \
                if (key > tk) acc += sp(fast ? __uint_as_float(key) : kinv(key)); \
            }                                                                    \
            if (tid == 0) {                                                      \
                float tval = fast ? __uint_as_float(s_tkey) : kinv(s_tkey);      \
                acc += (float)s_krem * sp(tval);                                 \
            }                                                                    \
        }                                                                        \
        __syncthreads();                                                         \
    }

    // ---- row A ----
    SELECT_ROW(postA, s_cnta, s_lista, 0, prowA, trowA)

    // ---- row B ----
    if (tid == 0) s_ccnt = 0;
    if (tid < 128) ((uint4*)s_hist)[128 + tid] = make_uint4(0, 0, 0, 0);  // words [512,1024)
    __syncthreads();
    if (hasB) {
        SELECT_ROW(postB, s_cntb, s_listb, 512, prowB, trowB)
    }

    // ---- row C ----
    if (tid == 0) s_ccnt = 0;
    if (tid < 128) ((uint4*)s_hist)[256 + tid] = make_uint4(0, 0, 0, 0);  // words [1024,1536)
    __syncthreads();
    if (hasC) {
        SELECT_ROW(postC, s_cntc, s_listc, 1024, prowC, trowC)
    }
    #undef SELECT_ROW

    // ======== block reduce + global accumulate + last-block finalize ========
    #pragma unroll
    for (int off = 16; off; off >>= 1) acc += __shfl_down_sync(0xFFFFFFFFu, acc, off);
    if (lane == 0) s_accr[wid] = acc;
    __syncthreads();

    if (tid == 0) {
        float totL = 0.f;
        #pragma unroll
        for (int w = 0; w < NW; w++) totL += s_accr[w];
        atomicAdd(&g_loss, (double)totL);
        atomicAdd(&g_tsum, (double)(postA + postB + postC));
        __threadfence();
        unsigned done = atomicAdd(&g_done, 1u);
        if (done == gridDim.x - 1) {
            double L = atomicAdd(&g_loss, 0.0);
            double T = atomicAdd(&g_tsum, 0.0);
            out[0] = (float)(L / T);
            atomicExch((unsigned long long*)&g_loss, 0ull);
            atomicExch((unsigned long long*)&g_tsum, 0ull);
            __threadfence();
            atomicExch(&g_done, 0u);
        }
    }
}

extern "C" void kernel_launch(void* const* d_in, const int* in_sizes, int n_in,
                              void* d_out, int out_size) {
    const float* pred   = (const float*)d_in[0];
    const float* target = (const float*)d_in[1];
    float* out = (float*)d_out;
    int rows = in_sizes[0] / NC;
    int grid = (rows + 2) / 3;

    hardneg<<<grid, NT>>>(pred, target, out, rows);
}